// round 2
// baseline (speedup 1.0000x reference)
#include <cuda_runtime.h>
#include <cuda_bf16.h>
#include <mma.h>
#include <math.h>

using namespace nvcuda;

#define T_STEPS 128
#define BATCH   512
#define HID     512
#define ADIM    18
#define ROWS    (T_STEPS * BATCH)   // 65536

// ---------------- scratch (static __device__, no allocs) ----------------
__device__ float g_S0[(size_t)ROWS * HID];        // 134 MB
__device__ float g_S1[(size_t)ROWS * HID];        // 134 MB
__device__ float g_Xg[(size_t)ROWS * 3 * HID];    // 402 MB  x@[w_ir|w_iz|w_in]
__device__ float g_Hg[(size_t)BATCH * 3 * HID];   // h@[w_hr|w_hz|w_hn] per step
__device__ float g_h [(size_t)BATCH * HID];       // carry

// ---------------- TF32 WMMA GEMM: C[M,N] = A[M,K] @ B[K,N] ----------------
#define BM 64
#define BN 64
#define BK 32
#define LDA_S 36   // BK+4
#define LDB_S 68   // BN+4

__global__ void __launch_bounds__(128) gemm_tf32(
    const float* __restrict__ A, int lda,
    const float* __restrict__ B, int ldb,
    float* __restrict__ C, int ldc, int K)
{
    __shared__ float As[BM][LDA_S];
    __shared__ float Bs[BK][LDB_S];

    const int tid = threadIdx.x;
    const int wid = tid >> 5;
    const size_t m0 = (size_t)blockIdx.y * BM;
    const size_t n0 = (size_t)blockIdx.x * BN;
    const int wm = (wid >> 1) * 32;   // 2x2 warp grid, 32x32 per warp
    const int wn = (wid & 1) * 32;

    wmma::fragment<wmma::accumulator, 16, 16, 8, float> acc[2][2];
#pragma unroll
    for (int i = 0; i < 2; i++)
#pragma unroll
        for (int j = 0; j < 2; j++) wmma::fill_fragment(acc[i][j], 0.0f);

    for (int k0 = 0; k0 < K; k0 += BK) {
        // A tile 64x32 = 512 float4, 4 per thread
#pragma unroll
        for (int l = 0; l < 4; l++) {
            int f = tid + l * 128;
            int r = f >> 3, c = (f & 7) * 4;
            float4 v = *(const float4*)(A + (m0 + r) * (size_t)lda + k0 + c);
            As[r][c + 0] = wmma::__float_to_tf32(v.x);
            As[r][c + 1] = wmma::__float_to_tf32(v.y);
            As[r][c + 2] = wmma::__float_to_tf32(v.z);
            As[r][c + 3] = wmma::__float_to_tf32(v.w);
        }
        // B tile 32x64 = 512 float4
#pragma unroll
        for (int l = 0; l < 4; l++) {
            int f = tid + l * 128;
            int r = f >> 4, c = (f & 15) * 4;
            float4 v = *(const float4*)(B + (size_t)(k0 + r) * ldb + n0 + c);
            Bs[r][c + 0] = wmma::__float_to_tf32(v.x);
            Bs[r][c + 1] = wmma::__float_to_tf32(v.y);
            Bs[r][c + 2] = wmma::__float_to_tf32(v.z);
            Bs[r][c + 3] = wmma::__float_to_tf32(v.w);
        }
        __syncthreads();
#pragma unroll
        for (int kk = 0; kk < BK; kk += 8) {
            wmma::fragment<wmma::matrix_a, 16, 16, 8, wmma::precision::tf32, wmma::row_major> af[2];
            wmma::fragment<wmma::matrix_b, 16, 16, 8, wmma::precision::tf32, wmma::row_major> bf[2];
            wmma::load_matrix_sync(af[0], &As[wm][kk], LDA_S);
            wmma::load_matrix_sync(af[1], &As[wm + 16][kk], LDA_S);
            wmma::load_matrix_sync(bf[0], &Bs[kk][wn], LDB_S);
            wmma::load_matrix_sync(bf[1], &Bs[kk][wn + 16], LDB_S);
#pragma unroll
            for (int i = 0; i < 2; i++)
#pragma unroll
                for (int j = 0; j < 2; j++)
                    wmma::mma_sync(acc[i][j], af[i], bf[j], acc[i][j]);
        }
        __syncthreads();
    }
#pragma unroll
    for (int i = 0; i < 2; i++)
#pragma unroll
        for (int j = 0; j < 2; j++)
            wmma::store_matrix_sync(C + (m0 + wm + 16 * i) * (size_t)ldc + n0 + wn + 16 * j,
                                    acc[i][j], ldc, wmma::mem_row_major);
}

// Three-B variant: C[M,1536] = A[M,512] @ concat(B0,B1,B2).  grid.x = 24.
__global__ void __launch_bounds__(128) gemm3_tf32(
    const float* __restrict__ A,
    const float* __restrict__ B0, const float* __restrict__ B1, const float* __restrict__ B2,
    float* __restrict__ C)
{
    __shared__ float As[BM][LDA_S];
    __shared__ float Bs[BK][LDB_S];

    const int tid = threadIdx.x;
    const int wid = tid >> 5;
    const size_t m0 = (size_t)blockIdx.y * BM;
    const int mat = blockIdx.x >> 3;
    const int bn0 = (blockIdx.x & 7) * 64;
    const size_t n0 = (size_t)blockIdx.x * BN;   // output col in ldc=1536
    const float* B = (mat == 0) ? B0 : (mat == 1 ? B1 : B2);
    const int wm = (wid >> 1) * 32;
    const int wn = (wid & 1) * 32;

    wmma::fragment<wmma::accumulator, 16, 16, 8, float> acc[2][2];
#pragma unroll
    for (int i = 0; i < 2; i++)
#pragma unroll
        for (int j = 0; j < 2; j++) wmma::fill_fragment(acc[i][j], 0.0f);

    for (int k0 = 0; k0 < HID; k0 += BK) {
#pragma unroll
        for (int l = 0; l < 4; l++) {
            int f = tid + l * 128;
            int r = f >> 3, c = (f & 7) * 4;
            float4 v = *(const float4*)(A + (m0 + r) * (size_t)HID + k0 + c);
            As[r][c + 0] = wmma::__float_to_tf32(v.x);
            As[r][c + 1] = wmma::__float_to_tf32(v.y);
            As[r][c + 2] = wmma::__float_to_tf32(v.z);
            As[r][c + 3] = wmma::__float_to_tf32(v.w);
        }
#pragma unroll
        for (int l = 0; l < 4; l++) {
            int f = tid + l * 128;
            int r = f >> 4, c = (f & 15) * 4;
            float4 v = *(const float4*)(B + (size_t)(k0 + r) * HID + bn0 + c);
            Bs[r][c + 0] = wmma::__float_to_tf32(v.x);
            Bs[r][c + 1] = wmma::__float_to_tf32(v.y);
            Bs[r][c + 2] = wmma::__float_to_tf32(v.z);
            Bs[r][c + 3] = wmma::__float_to_tf32(v.w);
        }
        __syncthreads();
#pragma unroll
        for (int kk = 0; kk < BK; kk += 8) {
            wmma::fragment<wmma::matrix_a, 16, 16, 8, wmma::precision::tf32, wmma::row_major> af[2];
            wmma::fragment<wmma::matrix_b, 16, 16, 8, wmma::precision::tf32, wmma::row_major> bf[2];
            wmma::load_matrix_sync(af[0], &As[wm][kk], LDA_S);
            wmma::load_matrix_sync(af[1], &As[wm + 16][kk], LDA_S);
            wmma::load_matrix_sync(bf[0], &Bs[kk][wn], LDB_S);
            wmma::load_matrix_sync(bf[1], &Bs[kk][wn + 16], LDB_S);
#pragma unroll
            for (int i = 0; i < 2; i++)
#pragma unroll
                for (int j = 0; j < 2; j++)
                    wmma::mma_sync(acc[i][j], af[i], bf[j], acc[i][j]);
        }
        __syncthreads();
    }
#pragma unroll
    for (int i = 0; i < 2; i++)
#pragma unroll
        for (int j = 0; j < 2; j++)
            wmma::store_matrix_sync(C + (m0 + wm + 16 * i) * (size_t)(3 * HID) + n0 + wn + 16 * j,
                                    acc[i][j], 3 * HID, wmma::mem_row_major);
}

// ---------------- LayerNorm(+bias, +optional one-hot row) + ReLU ----------------
// one block per row, 128 threads x 4 cols
__global__ void __launch_bounds__(128) ln_relu_kernel(
    const float* __restrict__ in, float* __restrict__ out,
    const float* __restrict__ addb,
    const float* __restrict__ lns, const float* __restrict__ lnb,
    const float* __restrict__ w_oh,   // nullable: w0 (rows 512.. hold one-hot part)
    const int* __restrict__ acts)     // nullable
{
    const int row = blockIdx.x;
    const int tid = threadIdx.x;
    const float* ip = in + (size_t)row * HID;

    float4 v = *(const float4*)(ip + tid * 4);
    float4 a = *(const float4*)(addb + tid * 4);
    v.x += a.x; v.y += a.y; v.z += a.z; v.w += a.w;
    if (w_oh) {
        const float* oh = w_oh + (size_t)(512 + acts[row]) * HID;
        float4 o = *(const float4*)(oh + tid * 4);
        v.x += o.x; v.y += o.y; v.z += o.z; v.w += o.w;
    }
    float sum = v.x + v.y + v.z + v.w;
    float sq  = v.x * v.x + v.y * v.y + v.z * v.z + v.w * v.w;

    __shared__ float red[8];
#pragma unroll
    for (int off = 16; off > 0; off >>= 1) {
        sum += __shfl_down_sync(0xFFFFFFFFu, sum, off);
        sq  += __shfl_down_sync(0xFFFFFFFFu, sq,  off);
    }
    if ((tid & 31) == 0) { red[tid >> 5] = sum; red[4 + (tid >> 5)] = sq; }
    __syncthreads();
    float ts = red[0] + red[1] + red[2] + red[3];
    float tq = red[4] + red[5] + red[6] + red[7];
    float mean = ts * (1.0f / HID);
    float var  = tq * (1.0f / HID) - mean * mean;
    float inv  = rsqrtf(var + 1e-6f);

    float4 sc = *(const float4*)(lns + tid * 4);
    float4 bb = *(const float4*)(lnb + tid * 4);
    float4 r;
    r.x = fmaxf((v.x - mean) * inv * sc.x + bb.x, 0.0f);
    r.y = fmaxf((v.y - mean) * inv * sc.y + bb.y, 0.0f);
    r.z = fmaxf((v.z - mean) * inv * sc.z + bb.z, 0.0f);
    r.w = fmaxf((v.w - mean) * inv * sc.w + bb.w, 0.0f);
    *(float4*)(out + (size_t)row * HID + tid * 4) = r;
}

// ---------------- initial done-mask: h = done[0] ? 0 : hidden_in ----------------
__global__ void mask0_kernel(const float* __restrict__ hidden_in,
                             const int* __restrict__ dones)
{
    int i = blockIdx.x * blockDim.x + threadIdx.x;   // 262144
    int b = i >> 9;
    g_h[i] = dones[b] ? 0.0f : hidden_in[i];
}

__device__ __forceinline__ float sigm(float x) { return 1.0f / (1.0f + expf(-x)); }

// ---------------- per-step gate fusion ----------------
// grid = BATCH blocks, 256 threads x 2 cols.
// writes y_t (unmasked h_new) into g_S0, next-step-masked h into g_h,
// and for the final step the new_hidden into d_out.
__global__ void __launch_bounds__(256) gate_kernel(
    int t,
    const float* __restrict__ b_ir, const float* __restrict__ b_iz,
    const float* __restrict__ b_in, const float* __restrict__ b_hn,
    const int* __restrict__ dones,
    float* __restrict__ out_hidden)
{
    const int b = blockIdx.x;
    const size_t rowg = (size_t)t * BATCH + b;
    const float* xg = g_Xg + rowg * (3 * HID);
    const float* hg = g_Hg + (size_t)b * (3 * HID);
    float* hrow = g_h + (size_t)b * HID;
    float* yrow = g_S0 + rowg * HID;
    const bool last = (t == T_STEPS - 1);
    const int dn = last ? 0 : dones[(t + 1) * BATCH + b];

#pragma unroll
    for (int i = 0; i < 2; i++) {
        int c = threadIdx.x + i * 256;
        float r = sigm(xg[c] + b_ir[c] + hg[c]);
        float z = sigm(xg[512 + c] + b_iz[c] + hg[512 + c]);
        float n = tanhf(xg[1024 + c] + b_in[c] + r * (hg[1024 + c] + b_hn[c]));
        float h = hrow[c];
        float hn = (1.0f - z) * n + z * h;
        yrow[c] = hn;
        hrow[c] = dn ? 0.0f : hn;
        if (last) out_hidden[(size_t)b * HID + c] = hn;
    }
}

// ---------------- output head: q = Y @ w_out + b_out ----------------
__global__ void __launch_bounds__(256) qout_kernel(
    const float* __restrict__ w_out, const float* __restrict__ b_out,
    float* __restrict__ q)
{
    __shared__ float ws[HID * ADIM];   // 36 KB
    for (int i = threadIdx.x; i < HID * ADIM; i += 256) ws[i] = w_out[i];
    __syncthreads();

    const size_t row = (size_t)blockIdx.x * 256 + threadIdx.x;
    const float* y = g_S0 + row * HID;
    float acc[ADIM];
#pragma unroll
    for (int a = 0; a < ADIM; a++) acc[a] = b_out[a];

    for (int c = 0; c < HID; c += 4) {
        float4 v = *(const float4*)(y + c);
        float yv[4] = {v.x, v.y, v.z, v.w};
#pragma unroll
        for (int j = 0; j < 4; j++)
#pragma unroll
            for (int a = 0; a < ADIM; a++)
                acc[a] = fmaf(yv[j], ws[(c + j) * ADIM + a], acc[a]);
    }
    float* qp = q + row * ADIM;
#pragma unroll
    for (int a = 0; a < ADIM; a++) qp[a] = acc[a];
}

// ---------------- launch ----------------
extern "C" void kernel_launch(void* const* d_in, const int* in_sizes, int n_in,
                              void* d_out, int out_size)
{
    const float* hidden    = (const float*)d_in[0];
    const float* obs       = (const float*)d_in[1];
    const int*   dones     = (const int*)d_in[2];
    const int*   last_acts = (const int*)d_in[3];
    const float* w0   = (const float*)d_in[4];
    const float* b0   = (const float*)d_in[5];
    const float* ln0s = (const float*)d_in[6];
    const float* ln0b = (const float*)d_in[7];
    const float* w1   = (const float*)d_in[8];
    const float* b1   = (const float*)d_in[9];
    const float* ln1s = (const float*)d_in[10];
    const float* ln1b = (const float*)d_in[11];
    const float* w_ir = (const float*)d_in[12];
    const float* b_ir = (const float*)d_in[13];
    const float* w_iz = (const float*)d_in[14];
    const float* b_iz = (const float*)d_in[15];
    const float* w_in = (const float*)d_in[16];
    const float* b_in = (const float*)d_in[17];
    const float* w_hr = (const float*)d_in[18];
    const float* w_hz = (const float*)d_in[19];
    const float* w_hn = (const float*)d_in[20];
    const float* b_hn = (const float*)d_in[21];
    const float* w_out = (const float*)d_in[22];
    const float* b_out = (const float*)d_in[23];

    float* out_hidden = (float*)d_out;                      // [B, H]
    float* out_q      = (float*)d_out + (size_t)BATCH * HID;  // [T, B, ADIM]

    float *S0, *S1, *Xg, *Hg, *h;
    cudaGetSymbolAddress((void**)&S0, g_S0);
    cudaGetSymbolAddress((void**)&S1, g_S1);
    cudaGetSymbolAddress((void**)&Xg, g_Xg);
    cudaGetSymbolAddress((void**)&Hg, g_Hg);
    cudaGetSymbolAddress((void**)&h,  g_h);

    dim3 gBig(HID / BN, ROWS / BM);        // (8, 1024)
    dim3 g3Big(3 * HID / BN, ROWS / BM);   // (24, 1024)
    dim3 g3Scan(3 * HID / BN, BATCH / BM); // (24, 8)

    // Encoder layer 0: obs part of x @ w0 (K=512); one-hot + b0 folded into LN.
    gemm_tf32<<<gBig, 128>>>(obs, HID, w0, HID, S0, HID, HID);
    ln_relu_kernel<<<ROWS, 128>>>(S0, S1, b0, ln0s, ln0b, w0, last_acts);
    // Encoder layer 1
    gemm_tf32<<<gBig, 128>>>(S1, HID, w1, HID, S0, HID, HID);
    ln_relu_kernel<<<ROWS, 128>>>(S0, S1, b1, ln1s, ln1b, nullptr, nullptr);
    // Hoisted input-gate GEMM: Xg = E2 @ [w_ir | w_iz | w_in]
    gemm3_tf32<<<g3Big, 128>>>(S1, w_ir, w_iz, w_in, Xg);
    // Initial carry mask
    mask0_kernel<<<(BATCH * HID) / 256, 256>>>(hidden, dones);

    // Sequential GRU scan
    for (int t = 0; t < T_STEPS; t++) {
        gemm3_tf32<<<g3Scan, 128>>>(h, w_hr, w_hz, w_hn, Hg);
        gate_kernel<<<BATCH, 256>>>(t, b_ir, b_iz, b_in, b_hn, dones, out_hidden);
    }

    // Output head
    qout_kernel<<<ROWS / 256, 256>>>(w_out, b_out, out_q);
}